// round 4
// baseline (speedup 1.0000x reference)
#include <cuda_runtime.h>

// MWPT: 3-level wavelet packet transform, fused, polyphase smem layout,
// gmem stores issued directly from compute registers (no read-back passes).
//
// conv: out[n] = sum_k in[(2n + k - 3) mod L] * w[k]  (circular, stride 2)
// hi-pass QMF: wh[k] = (-1)^k * wl[7-k]
// out = concat(level1 [128,2,32768], level2 [128,4,16384], level3 [128,8,8192])
// level2 node order [b0,b2,b6,b4]; level3 [c0,c1,c3,c2,c6,c7,c5,c4].
//
// Local index bases chosen so owned ranges are 4-aligned:
//  x staged from jbase = 8n0-28 (even): xE[i]=x[jbase+2i], xO[i]=x[jbase+2i+1]
//  a_alpha (alpha = m - 4n0 + 12), computed alpha in [0, 4*N3+24):
//      a_alpha = sum_j xO[alpha+j] wl[2j] + xE[alpha+j+1] wl[2j+1]
//      owned alpha in [12, 12+4*N3); stored aE[v]=a_{2v}, aO[v]=a_{2v+1}
//  b_beta  (beta = l - 2n0 + 4), computed beta in [0, 2*N3+8):
//      b_beta  = sum_j aO[beta+j] wl[2j] + aE[beta+j+1] wl[2j+1]
//      owned beta in [4, 4+2*N3); stored bE[v]=b_{2v}, bO[v]=b_{2v+1}
//  c_r     (r = i - n0), r in [0, N3):
//      c_r     = sum_j bO[r+j]  wl[2j] + bE[r+j+1]  wl[2j+1]
// Same polyphase form at every level.

namespace {
constexpr int T   = 65536, MSK = T - 1, KS = 8;
constexpr int N3  = 512;
constexpr int THREADS = 256;
constexpr int XSZ = 4 * N3 + 32;     // 2080 per parity (2076 used)
constexpr int ASZ = 2 * N3 + 16;     // 1040 per array  (1036 used)
constexpr int BSZ = N3 + 8;          // 520  per array  (516 used)
constexpr int XREG = 2 * XSZ;        // 4160 floats; aliased by 8*BSZ = 4160
constexpr int SMEM_FLOATS = XREG + 4 * ASZ;   // 8320
constexpr int SMEM_BYTES  = SMEM_FLOATS * 4;  // 33280
constexpr long OUT2_BASE = 128L * 2 * 32768;
constexpr long OUT3_BASE = OUT2_BASE + 128L * 4 * 16384;
}

__device__ __forceinline__ void ld8(const float* s, float v[8]) {
    float4 a = *(const float4*)s;        // bases always 16B-aligned
    float4 b = *(const float4*)(s + 4);
    v[0]=a.x; v[1]=a.y; v[2]=a.z; v[3]=a.w;
    v[4]=b.x; v[5]=b.y; v[6]=b.z; v[7]=b.w;
}

// lo[p] = sum_j O[p+j]*wl[2j] + E[p+j+1]*wl[2j+1]; hi likewise with wh.
__device__ __forceinline__ void qmf4(const float O[8], const float E[8],
                                     const float wl[KS], const float wh[KS],
                                     float lo[4], float hi[4]) {
    #pragma unroll
    for (int p = 0; p < 4; ++p) {
        float l = 0.f, h = 0.f;
        #pragma unroll
        for (int j = 0; j < 4; ++j) {
            float o = O[p + j], e = E[p + j + 1];
            l += o * wl[2*j] + e * wl[2*j+1];
            h += o * wh[2*j] + e * wh[2*j+1];
        }
        lo[p] = l; hi[p] = h;
    }
}

__global__ __launch_bounds__(THREADS, 6) void mwpt_kernel(
    const float* __restrict__ x,
    const float* __restrict__ kern,
    float* __restrict__ out)
{
    extern __shared__ float sm[];
    float* xE  = sm;                 // [XSZ]
    float* xO  = sm + XSZ;           // [XSZ]
    float* aE0 = sm + XREG;          // [ASZ] x4
    float* aO0 = aE0 + ASZ;
    float* aE4 = aO0 + ASZ;
    float* aO4 = aE4 + ASZ;
    // b arrays alias x region (x dead after level-1 compute)
    // parent n in {b0,b2,b4,b6}: bE = sm + n*2*BSZ, bO = bE + BSZ

    const int b   = blockIdx.y;
    const int n0  = blockIdx.x * N3;
    const int tid = threadIdx.x;

    float wl[KS], wh[KS];
    #pragma unroll
    for (int k = 0; k < KS; ++k) wl[k] = __ldg(&kern[k]);
    #pragma unroll
    for (int k = 0; k < KS; ++k) wh[k] = (k & 1) ? -wl[KS-1-k] : wl[KS-1-k];

    // ---- Stage x, parity-split (aligned LDG.64, conflict-free STS.32) ----
    {
        const int jbase = 8 * n0 - 28;                 // even
        const float* xb = x + (size_t)b * T;
        for (int i = tid; i < 4 * N3 + 28; i += THREADS) {
            float2 v = *(const float2*)(xb + ((jbase + 2*i) & MSK));
            xE[i] = v.x; xO[i] = v.y;
        }
    }
    __syncthreads();

    // ---- Level 1: chunks g in [0, N3+6); owned g in [3, 3+N3) ----
    {
        float* o1 = out + (size_t)b * (2 * 32768) + 4 * n0;
        for (int g = tid; g < N3 + 6; g += THREADS) {
            float o8[8], e8[8], lo[4], hi[4];
            ld8(xO + 4*g, o8);
            ld8(xE + 4*g, e8);
            qmf4(o8, e8, wl, wh, lo, hi);
            *(float2*)(aE0 + 2*g) = make_float2(lo[0], lo[2]);
            *(float2*)(aO0 + 2*g) = make_float2(lo[1], lo[3]);
            *(float2*)(aE4 + 2*g) = make_float2(hi[0], hi[2]);
            *(float2*)(aO4 + 2*g) = make_float2(hi[1], hi[3]);
            if (g >= 3 && g < 3 + N3) {
                *(float4*)(o1 + 4*(g-3))         = make_float4(lo[0], lo[1], lo[2], lo[3]);
                *(float4*)(o1 + 32768 + 4*(g-3)) = make_float4(hi[0], hi[1], hi[2], hi[3]);
            }
        }
    }
    __syncthreads();

    // ---- Level 2: per parent, chunks h in [0, N3/2+2); owned h in [1, 1+N3/2) ----
    {
        float* o2 = out + OUT2_BASE + (size_t)b * (4 * 16384) + 2 * n0;
        #pragma unroll
        for (int par = 0; par < 2; ++par) {
            const float* AE = par ? aE4 : aE0;
            const float* AO = par ? aO4 : aO0;
            float* bLoE = sm + (2*par)     * (2*BSZ);
            float* bLoO = bLoE + BSZ;
            float* bHiE = sm + (2*par + 1) * (2*BSZ);
            float* bHiO = bHiE + BSZ;
            const int pos_lo = par ? 3 : 0;    // b0->0, b4->3
            const int pos_hi = par ? 2 : 1;    // b2->1, b6->2
            for (int h = tid; h < N3/2 + 2; h += THREADS) {
                float o8[8], e8[8], lo[4], hi[4];
                ld8(AO + 4*h, o8);
                ld8(AE + 4*h, e8);
                qmf4(o8, e8, wl, wh, lo, hi);
                *(float2*)(bLoE + 2*h) = make_float2(lo[0], lo[2]);
                *(float2*)(bLoO + 2*h) = make_float2(lo[1], lo[3]);
                *(float2*)(bHiE + 2*h) = make_float2(hi[0], hi[2]);
                *(float2*)(bHiO + 2*h) = make_float2(hi[1], hi[3]);
                if (h >= 1 && h < 1 + N3/2) {
                    *(float4*)(o2 + pos_lo * 16384 + 4*(h-1)) =
                        make_float4(lo[0], lo[1], lo[2], lo[3]);
                    *(float4*)(o2 + pos_hi * 16384 + 4*(h-1)) =
                        make_float4(hi[0], hi[1], hi[2], hi[3]);
                }
            }
        }
    }
    __syncthreads();

    // ---- Level 3: 4 parents x N3/4 chunks, stream straight to gmem ----
    // parent n (b0,b2,b4,b6) -> children pos_lo={0,3,7,4}, pos_hi={1,2,6,5}
    {
        float* o3 = out + OUT3_BASE + (size_t)b * (8 * 8192) + n0;
        #pragma unroll
        for (int it = 0; it < (4 * (N3/4)) / THREADS; ++it) {
            const int t   = it * THREADS + tid;
            const int par = t >> 7;                 // warp-uniform (N3/4 = 128)
            const int g   = t & (N3/4 - 1);
            const float* bE = sm + par * (2*BSZ);
            const float* bO = bE + BSZ;
            float o8[8], e8[8], lo[4], hi[4];
            ld8(bO + 4*g, o8);
            ld8(bE + 4*g, e8);
            qmf4(o8, e8, wl, wh, lo, hi);
            const int pos_lo = (par == 0) ? 0 : (par == 1) ? 3 : (par == 2) ? 7 : 4;
            const int pos_hi = (par == 0) ? 1 : (par == 1) ? 2 : (par == 2) ? 6 : 5;
            *(float4*)(o3 + pos_lo * 8192 + 4*g) = make_float4(lo[0], lo[1], lo[2], lo[3]);
            *(float4*)(o3 + pos_hi * 8192 + 4*g) = make_float4(hi[0], hi[1], hi[2], hi[3]);
        }
    }
}

extern "C" void kernel_launch(void* const* d_in, const int* in_sizes, int n_in,
                              void* d_out, int out_size)
{
    const float* x    = (const float*)d_in[0];
    const float* kern = (const float*)d_in[1];
    float* out        = (float*)d_out;

    cudaFuncSetAttribute(mwpt_kernel,
                         cudaFuncAttributeMaxDynamicSharedMemorySize,
                         SMEM_BYTES);

    dim3 grid(8192 / N3, 128);   // 16 x 128 = 2048 blocks
    mwpt_kernel<<<grid, THREADS, SMEM_BYTES>>>(x, kern, out);
}

// round 5
// speedup vs baseline: 1.7089x; 1.7089x over previous
#include <cuda_runtime.h>

// MWPT: 3-level wavelet packet transform, fused, polyphase smem layout.
// Stores issued from compute registers; owned chunks handled by BRANCH-FREE
// fully-unrolled main loops, halo chunks by a tiny side loop (first warp).
//
// conv: out[n] = sum_k in[(2n + k - 3) mod L] * w[k]  (circular, stride 2)
// hi-pass QMF: wh[k] = (-1)^k * wl[7-k]
// out = concat(level1 [128,2,32768], level2 [128,4,16384], level3 [128,8,8192])
// level2 node order [b0,b2,b6,b4]; level3 [c0,c1,c3,c2,c6,c7,c5,c4].
//
// Index algebra (validated in R4):
//  x staged from jbase = 8n0-28 (even): xE[i]=x[jbase+2i], xO[i]=x[jbase+2i+1]
//  a_alpha (alpha = m-4n0+12), alpha in [0,2072):
//      a_alpha = sum_j xO[alpha+j]wl[2j] + xE[alpha+j+1]wl[2j+1]
//      owned alpha in [12,12+2048); aE[v]=a_{2v}, aO[v]=a_{2v+1}
//  b_beta (beta = l-2n0+4), beta in [0,1032):
//      b_beta = sum_j aO[beta+j]wl[2j] + aE[beta+j+1]wl[2j+1]
//      owned beta in [4,4+1024); bE[v]=b_{2v}, bO[v]=b_{2v+1}
//  c_r (r = i-n0) in [0,512): c_r = sum_j bO[r+j]wl[2j] + bE[r+j+1]wl[2j+1]

namespace {
constexpr int T   = 65536, MSK = T - 1, KS = 8;
constexpr int N3  = 512;
constexpr int THREADS = 256;
constexpr int XSZ = 2080;            // per parity (2076 used)
constexpr int ASZ = 1040;            // per array  (1036 used)
constexpr int BSZ = 520;             // per array  (516 used)
constexpr int XREG = 2 * XSZ;        // 4160 floats; aliased by 8*BSZ = 4160
constexpr int SMEM_FLOATS = XREG + 4 * ASZ;   // 8320
constexpr int SMEM_BYTES  = SMEM_FLOATS * 4;  // 33280
constexpr long OUT2_BASE = 128L * 2 * 32768;
constexpr long OUT3_BASE = OUT2_BASE + 128L * 4 * 16384;
}

__device__ __forceinline__ void ld8(const float* s, float v[8]) {
    float4 a = *(const float4*)s;        // bases always 16B-aligned
    float4 b = *(const float4*)(s + 4);
    v[0]=a.x; v[1]=a.y; v[2]=a.z; v[3]=a.w;
    v[4]=b.x; v[5]=b.y; v[6]=b.z; v[7]=b.w;
}

// lo[p] = sum_j O[p+j]*wl[2j] + E[p+j+1]*wl[2j+1]; hi likewise with wh.
__device__ __forceinline__ void qmf4(const float O[8], const float E[8],
                                     const float wl[KS], const float wh[KS],
                                     float lo[4], float hi[4]) {
    #pragma unroll
    for (int p = 0; p < 4; ++p) {
        float l = 0.f, h = 0.f;
        #pragma unroll
        for (int j = 0; j < 4; ++j) {
            float o = O[p + j], e = E[p + j + 1];
            l += o * wl[2*j] + e * wl[2*j+1];
            h += o * wh[2*j] + e * wh[2*j+1];
        }
        lo[p] = l; hi[p] = h;
    }
}

__global__ __launch_bounds__(THREADS, 6) void mwpt_kernel(
    const float* __restrict__ x,
    const float* __restrict__ kern,
    float* __restrict__ out)
{
    extern __shared__ float sm[];
    float* xE  = sm;                 // [XSZ]
    float* xO  = sm + XSZ;           // [XSZ]
    float* aE0 = sm + XREG;          // [ASZ] x4
    float* aO0 = aE0 + ASZ;
    float* aE4 = aO0 + ASZ;
    float* aO4 = aE4 + ASZ;
    // b arrays alias x region (x dead after level-1):
    // parent n in {b0,b2,b4,b6}: bE = sm + n*2*BSZ, bO = bE + BSZ

    const int b   = blockIdx.y;
    const int n0  = blockIdx.x * N3;
    const int tid = threadIdx.x;

    float wl[KS], wh[KS];
    #pragma unroll
    for (int k = 0; k < KS; ++k) wl[k] = __ldg(&kern[k]);
    #pragma unroll
    for (int k = 0; k < KS; ++k) wh[k] = (k & 1) ? -wl[KS-1-k] : wl[KS-1-k];

    // ---- Stage x, parity-split. jbase ≡ 0 mod 4 -> aligned LDG.128. ----
    {
        const int jbase = 8 * n0 - 28;
        const float* xb = x + (size_t)b * T;
        #pragma unroll
        for (int it = 0; it < 5; ++it) {           // 5*256 = 1280 >= 1040
            const int i4 = it * THREADS + tid;     // float4 index (2 E + 2 O)
            if (i4 < 1040) {
                float4 v = *(const float4*)(xb + ((jbase + 4 * i4) & MSK));
                *(float2*)(xE + 2 * i4) = make_float2(v.x, v.z);
                *(float2*)(xO + 2 * i4) = make_float2(v.y, v.w);
            }
        }
    }
    __syncthreads();

    // ================= Level 1 =================
    {
        float* o1 = out + (size_t)b * (2 * 32768) + 4 * n0;
        // halo chunks {0,1,2,515,516,517}: compute only (one warp)
        if (tid < 6) {
            const int g = (tid < 3) ? tid : 512 + tid;
            float o8[8], e8[8], lo[4], hi[4];
            ld8(xO + 4*g, o8);
            ld8(xE + 4*g, e8);
            qmf4(o8, e8, wl, wh, lo, hi);
            *(float2*)(aE0 + 2*g) = make_float2(lo[0], lo[2]);
            *(float2*)(aO0 + 2*g) = make_float2(lo[1], lo[3]);
            *(float2*)(aE4 + 2*g) = make_float2(hi[0], hi[2]);
            *(float2*)(aO4 + 2*g) = make_float2(hi[1], hi[3]);
        }
        // owned chunks: g = g'+3, g' in [0,512); branch-free, 2 unrolled trips
        #pragma unroll
        for (int it = 0; it < 2; ++it) {
            const int gp = it * THREADS + tid;
            const int g  = gp + 3;
            float o8[8], e8[8], lo[4], hi[4];
            ld8(xO + 4*g, o8);
            ld8(xE + 4*g, e8);
            qmf4(o8, e8, wl, wh, lo, hi);
            *(float2*)(aE0 + 2*g) = make_float2(lo[0], lo[2]);
            *(float2*)(aO0 + 2*g) = make_float2(lo[1], lo[3]);
            *(float2*)(aE4 + 2*g) = make_float2(hi[0], hi[2]);
            *(float2*)(aO4 + 2*g) = make_float2(hi[1], hi[3]);
            *(float4*)(o1 + 4*gp)         = make_float4(lo[0], lo[1], lo[2], lo[3]);
            *(float4*)(o1 + 32768 + 4*gp) = make_float4(hi[0], hi[1], hi[2], hi[3]);
        }
    }
    __syncthreads();

    // ================= Level 2 =================
    {
        float* o2 = out + OUT2_BASE + (size_t)b * (4 * 16384) + 2 * n0;
        // halo: h in {0, 257} per parent: 4 items (one warp)
        if (tid < 4) {
            const int par = tid >> 1;
            const int h   = (tid & 1) ? 257 : 0;
            const float* AE = par ? aE4 : aE0;
            const float* AO = par ? aO4 : aO0;
            float* bLoE = sm + (2*par)     * (2*BSZ);
            float* bHiE = sm + (2*par + 1) * (2*BSZ);
            float o8[8], e8[8], lo[4], hi[4];
            ld8(AO + 4*h, o8);
            ld8(AE + 4*h, e8);
            qmf4(o8, e8, wl, wh, lo, hi);
            *(float2*)(bLoE + 2*h)       = make_float2(lo[0], lo[2]);
            *(float2*)(bLoE + BSZ + 2*h) = make_float2(lo[1], lo[3]);
            *(float2*)(bHiE + 2*h)       = make_float2(hi[0], hi[2]);
            *(float2*)(bHiE + BSZ + 2*h) = make_float2(hi[1], hi[3]);
        }
        // owned: h = h'+1, h' = tid in [0,256); one trip per parent, unrolled
        #pragma unroll
        for (int par = 0; par < 2; ++par) {
            const float* AE = par ? aE4 : aE0;
            const float* AO = par ? aO4 : aO0;
            float* bLoE = sm + (2*par)     * (2*BSZ);
            float* bHiE = sm + (2*par + 1) * (2*BSZ);
            const int pos_lo = par ? 3 : 0;   // b0->0, b4->3
            const int pos_hi = par ? 2 : 1;   // b2->1, b6->2
            const int h = tid + 1;
            float o8[8], e8[8], lo[4], hi[4];
            ld8(AO + 4*h, o8);
            ld8(AE + 4*h, e8);
            qmf4(o8, e8, wl, wh, lo, hi);
            *(float2*)(bLoE + 2*h)       = make_float2(lo[0], lo[2]);
            *(float2*)(bLoE + BSZ + 2*h) = make_float2(lo[1], lo[3]);
            *(float2*)(bHiE + 2*h)       = make_float2(hi[0], hi[2]);
            *(float2*)(bHiE + BSZ + 2*h) = make_float2(hi[1], hi[3]);
            *(float4*)(o2 + pos_lo * 16384 + 4*tid) =
                make_float4(lo[0], lo[1], lo[2], lo[3]);
            *(float4*)(o2 + pos_hi * 16384 + 4*tid) =
                make_float4(hi[0], hi[1], hi[2], hi[3]);
        }
    }
    __syncthreads();

    // ================= Level 3 =================
    // parent n (b0,b2,b4,b6) -> children pos_lo={0,3,7,4}, pos_hi={1,2,6,5}
    {
        float* o3 = out + OUT3_BASE + (size_t)b * (8 * 8192) + n0;
        #pragma unroll
        for (int it = 0; it < 2; ++it) {
            const int t   = it * THREADS + tid;
            const int par = t >> 7;               // warp-uniform
            const int g   = t & 127;
            const float* bE = sm + par * (2*BSZ);
            const float* bO = bE + BSZ;
            float o8[8], e8[8], lo[4], hi[4];
            ld8(bO + 4*g, o8);
            ld8(bE + 4*g, e8);
            qmf4(o8, e8, wl, wh, lo, hi);
            const int pos_lo = (par == 0) ? 0 : (par == 1) ? 3 : (par == 2) ? 7 : 4;
            const int pos_hi = (par == 0) ? 1 : (par == 1) ? 2 : (par == 2) ? 6 : 5;
            *(float4*)(o3 + pos_lo * 8192 + 4*g) = make_float4(lo[0], lo[1], lo[2], lo[3]);
            *(float4*)(o3 + pos_hi * 8192 + 4*g) = make_float4(hi[0], hi[1], hi[2], hi[3]);
        }
    }
}

extern "C" void kernel_launch(void* const* d_in, const int* in_sizes, int n_in,
                              void* d_out, int out_size)
{
    const float* x    = (const float*)d_in[0];
    const float* kern = (const float*)d_in[1];
    float* out        = (float*)d_out;

    cudaFuncSetAttribute(mwpt_kernel,
                         cudaFuncAttributeMaxDynamicSharedMemorySize,
                         SMEM_BYTES);

    dim3 grid(8192 / N3, 128);   // 16 x 128 = 2048 blocks
    mwpt_kernel<<<grid, THREADS, SMEM_BYTES>>>(x, kern, out);
}